// round 4
// baseline (speedup 1.0000x reference)
#include <cuda_runtime.h>
#include <cuda_bf16.h>
#include <cstdint>

// ---------------------------------------------------------------------------
// Problem constants (fixed by the dataset)
// ---------------------------------------------------------------------------
#define N_NODES 50000
#define E_MAX   800000
#define D_IN    64
#define HID     128

// ---------------------------------------------------------------------------
// Scratch (no cudaMalloc allowed -> __device__ globals)
// ---------------------------------------------------------------------------
__device__ float d_deg [N_NODES];
__device__ float d_dis [N_NODES];
__device__ int   d_cnt [N_NODES];
__device__ int   d_indptr[N_NODES + 1];
__device__ int   d_cursor[N_NODES];
__device__ int2  d_payload[E_MAX];        // {src_row, norm as float bits}
__device__ float d_agg1[N_NODES * D_IN];
__device__ float d_h1  [N_NODES * HID];
__device__ float d_agg2[N_NODES * HID];
__device__ float d_AB  [N_NODES * 2 * HID];
__device__ float d_Wf  [HID * 2 * HID];   // fused W2 @ [Wc1_top | Wc1_bot]
__device__ float d_bf  [2 * HID];         // fused b2 @ Wc1 (+ bc1 in a-half)

// ---------------------------------------------------------------------------
// PTX helpers
// ---------------------------------------------------------------------------
__device__ __forceinline__ uint32_t f2tf32(float x) {
    uint32_t r;
    asm("cvt.rna.tf32.f32 %0, %1;" : "=r"(r) : "f"(x));
    return r;
}

__device__ __forceinline__ void mma_tf32(float* c, const uint32_t* a, const uint32_t* b) {
    asm volatile(
        "mma.sync.aligned.m16n8k8.row.col.f32.tf32.tf32.f32 "
        "{%0,%1,%2,%3}, {%4,%5,%6,%7}, {%8,%9}, {%0,%1,%2,%3};"
        : "+f"(c[0]), "+f"(c[1]), "+f"(c[2]), "+f"(c[3])
        : "r"(a[0]), "r"(a[1]), "r"(a[2]), "r"(a[3]), "r"(b[0]), "r"(b[1]));
}

// ---------------------------------------------------------------------------
// Degree / histogram / norm
// ---------------------------------------------------------------------------
__global__ void init_counts_kernel(float* deg, int* cnt, int n) {
    int i = blockIdx.x * blockDim.x + threadIdx.x;
    if (i < n) { deg[i] = 1.0f; cnt[i] = 0; }   // deg starts at 1 (self loop)
}

__global__ void count_kernel(const int* __restrict__ row,
                             const int* __restrict__ col,
                             float* deg, int* cnt, int E) {
    int e = blockIdx.x * blockDim.x + threadIdx.x;
    if (e >= E) return;
    atomicAdd(&deg[row[e]], 1.0f);
    atomicAdd(&cnt[col[e]], 1);
}

__global__ void compute_dis_kernel(const float* __restrict__ deg, float* dis, int n) {
    int i = blockIdx.x * blockDim.x + threadIdx.x;
    if (i < n) dis[i] = rsqrtf(deg[i]);
}

// ---------------------------------------------------------------------------
// Single-block exclusive scan over cnt -> indptr (N+1) and cursor copy
// ---------------------------------------------------------------------------
__global__ void __launch_bounds__(1024)
scan_kernel(const int* __restrict__ cnt, int* __restrict__ indptr,
            int* __restrict__ cursor, int n) {
    __shared__ int s[1024];
    const int T = 1024;
    int t = threadIdx.x;
    int chunk = (n + T - 1) / T;
    int b = t * chunk;
    int e = min(b + chunk, n);
    int sum = 0;
    for (int i = b; i < e; i++) sum += cnt[i];
    s[t] = sum;
    __syncthreads();
    // inclusive Hillis-Steele scan
    for (int off = 1; off < T; off <<= 1) {
        int v = (t >= off) ? s[t - off] : 0;
        __syncthreads();
        s[t] += v;
        __syncthreads();
    }
    int run = s[t] - sum;           // exclusive prefix for this chunk
    for (int i = b; i < e; i++) {
        indptr[i] = run;
        cursor[i] = run;
        run += cnt[i];
    }
    if (t == T - 1) indptr[n] = s[T - 1];
}

__global__ void fill_kernel(const int* __restrict__ row,
                            const int* __restrict__ col,
                            const float* __restrict__ dis,
                            int* __restrict__ cursor,
                            int2* __restrict__ payload, int E) {
    int e = blockIdx.x * blockDim.x + threadIdx.x;
    if (e >= E) return;
    int r = row[e];
    int c = col[e];
    float nrm = dis[r] * dis[c];
    int p = atomicAdd(&cursor[c], 1);
    payload[p] = make_int2(r, __float_as_int(nrm));
}

// ---------------------------------------------------------------------------
// CSR gather aggregation (no atomics). Warp per destination node.
// conv1: d=64 features, lane owns float2. conv2: h=128, lane owns float4.
// ---------------------------------------------------------------------------
__global__ void __launch_bounds__(256)
gather1_kernel(const float* __restrict__ x,
               const float* __restrict__ dis,
               const int* __restrict__ indptr,
               const int2* __restrict__ payload,
               float* __restrict__ agg1, int n) {
    int d    = blockIdx.x * 8 + (threadIdx.x >> 5);
    int lane = threadIdx.x & 31;
    if (d >= n) return;
    const float2* xp = (const float2*)x;     // 32 float2 per row
    float s = dis[d]; s *= s;
    float2 v = xp[(size_t)d * 32 + lane];
    float2 acc = make_float2(v.x * s, v.y * s);     // self loop
    int beg = indptr[d], end = indptr[d + 1];
    if (beg < end) {
        int2 pl = payload[beg];
        for (int i = beg; i < end; i++) {
            int2 cur = pl;
            if (i + 1 < end) pl = payload[i + 1];
            float nrm = __int_as_float(cur.y);
            float2 u = xp[(size_t)cur.x * 32 + lane];
            acc.x = fmaf(u.x, nrm, acc.x);
            acc.y = fmaf(u.y, nrm, acc.y);
        }
    }
    ((float2*)agg1)[(size_t)d * 32 + lane] = acc;
}

__global__ void __launch_bounds__(256)
gather2_kernel(const float* __restrict__ h1,
               const float* __restrict__ dis,
               const int* __restrict__ indptr,
               const int2* __restrict__ payload,
               float* __restrict__ agg2, int n) {
    int d    = blockIdx.x * 8 + (threadIdx.x >> 5);
    int lane = threadIdx.x & 31;
    if (d >= n) return;
    const float4* hp = (const float4*)h1;    // 32 float4 per row
    float s = dis[d]; s *= s;
    float4 v = hp[(size_t)d * 32 + lane];
    float4 acc = make_float4(v.x * s, v.y * s, v.z * s, v.w * s);  // self loop
    int beg = indptr[d], end = indptr[d + 1];
    if (beg < end) {
        int2 pl = payload[beg];
        for (int i = beg; i < end; i++) {
            int2 cur = pl;
            if (i + 1 < end) pl = payload[i + 1];
            float nrm = __int_as_float(cur.y);
            float4 u = hp[(size_t)cur.x * 32 + lane];
            acc.x = fmaf(u.x, nrm, acc.x);
            acc.y = fmaf(u.y, nrm, acc.y);
            acc.z = fmaf(u.z, nrm, acc.z);
            acc.w = fmaf(u.w, nrm, acc.w);
        }
    }
    ((float4*)agg2)[(size_t)d * 32 + lane] = acc;
}

// ---------------------------------------------------------------------------
// Weight fusion (tiled): Wf[k][j] = sum_t W2[k][t] * Wc1[(j>>7)*128 + t][j&127]
// Grid (4 k-tiles, 4 j-tiles), 256 threads. Tiles: A 32x128, B 128x64.
// ---------------------------------------------------------------------------
__global__ void __launch_bounds__(256)
fuse_weights_kernel(const float* __restrict__ W2,
                    const float* __restrict__ Wc1,
                    float* __restrict__ Wf) {
    __shared__ float sA[32 * 128];
    __shared__ float sB[128 * 64];
    int tid = threadIdx.x;
    int k0  = blockIdx.x * 32;
    int jt  = blockIdx.y;
    int half = jt >> 1;
    int j0   = (jt & 1) * 64;

    // load A: 32x128 floats = 1024 float4, 4 per thread
#pragma unroll
    for (int j = 0; j < 4; j++) {
        int i = tid + j * 256;
        *(float4*)&sA[i * 4] = *(const float4*)&W2[(size_t)(k0 + (i >> 5)) * HID + (i & 31) * 4];
    }
    // load B: 128x64 floats = 2048 float4, 8 per thread
#pragma unroll
    for (int j = 0; j < 8; j++) {
        int i = tid + j * 256;          // 0..2047
        int t = i >> 4, c4 = i & 15;
        *(float4*)&sB[t * 64 + c4 * 4] =
            *(const float4*)&Wc1[(size_t)(half * HID + t) * HID + j0 + c4 * 4];
    }
    __syncthreads();

    int tx = tid & 15;          // 4 j outputs
    int ty = tid >> 4;          // 2 k outputs
    float acc[2][4] = {};
#pragma unroll 4
    for (int t = 0; t < 128; t++) {
        float4 bv = *(const float4*)&sB[t * 64 + tx * 4];
        float a0 = sA[(ty * 2 + 0) * 128 + t];
        float a1 = sA[(ty * 2 + 1) * 128 + t];
        acc[0][0] = fmaf(a0, bv.x, acc[0][0]);
        acc[0][1] = fmaf(a0, bv.y, acc[0][1]);
        acc[0][2] = fmaf(a0, bv.z, acc[0][2]);
        acc[0][3] = fmaf(a0, bv.w, acc[0][3]);
        acc[1][0] = fmaf(a1, bv.x, acc[1][0]);
        acc[1][1] = fmaf(a1, bv.y, acc[1][1]);
        acc[1][2] = fmaf(a1, bv.z, acc[1][2]);
        acc[1][3] = fmaf(a1, bv.w, acc[1][3]);
    }
#pragma unroll
    for (int kk = 0; kk < 2; kk++)
        *(float4*)&Wf[(size_t)(k0 + ty * 2 + kk) * (2 * HID) + half * HID + j0 + tx * 4] =
            make_float4(acc[kk][0], acc[kk][1], acc[kk][2], acc[kk][3]);
}

__global__ void fuse_bias_kernel(const float* __restrict__ b2,
                                 const float* __restrict__ Wc1,
                                 const float* __restrict__ bc1,
                                 float* __restrict__ bf) {
    __shared__ float sb[HID];
    int j = threadIdx.x;        // 0..255
    if (j < HID) sb[j] = b2[j];
    __syncthreads();
    int half = j >> 7, jj = j & 127;
    float acc = (j < HID) ? bc1[j] : 0.0f;   // bc1 folded into the a-half
#pragma unroll 8
    for (int t = 0; t < HID; t++)
        acc = fmaf(sb[t], Wc1[(size_t)(half * HID + t) * HID + jj], acc);
    bf[j] = acc;
}

// ---------------------------------------------------------------------------
// TF32 tensor-core GEMM: C[M,NOUT] = A[M,K] @ W[K,NOUT] + bias (+relu)
// BM=128, N tile 128 (blockIdx.y picks half for NOUT=256), BK=32,
// 256 threads = 8 warps (4Mx2N), warp tile 32x64 via m16n8k8 tf32 mma.
// Fragment-major smem: every fragment fetch = 1 conflict-free LDS.128/64.
// ---------------------------------------------------------------------------
template<int K, int NOUT, bool RELU>
__global__ void __launch_bounds__(256, 2)
mma_gemm_kernel(const float* __restrict__ A, const float* __restrict__ W,
                const float* __restrict__ bias, float* __restrict__ C, int M) {
    constexpr int BM = 128, BK = 32;
    __shared__ uint32_t sA[4 * 8 * 32 * 4];   // [kt][mt][lane][reg]  16KB
    __shared__ uint32_t sB[4 * 16 * 32 * 2];  // [kt][nt][lane][reg]  16KB

    const int tid  = threadIdx.x;
    const int m0   = blockIdx.x * BM;
    const int n0   = blockIdx.y * 128;
    const int w    = tid >> 5, lane = tid & 31;
    const int wm   = (w & 3) * 32, wn = (w >> 2) * 64;
    const int g    = lane >> 2, tg = lane & 3;

    float acc[2][8][4];
#pragma unroll
    for (int m = 0; m < 2; m++)
#pragma unroll
        for (int n = 0; n < 8; n++)
#pragma unroll
            for (int c = 0; c < 4; c++) acc[m][n][c] = 0.0f;

    for (int k0 = 0; k0 < K; k0 += BK) {
        // --- A tile: 128x32 floats, permuted to mma-fragment order ---
#pragma unroll
        for (int j = 0; j < 4; j++) {
            int i  = tid + j * 256;          // 0..1023 float4 slots
            int r  = i >> 3, c4 = i & 7;
            int mm = m0 + r;
            float4 v = make_float4(0.f, 0.f, 0.f, 0.f);
            if (mm < M) v = *(const float4*)&A[(size_t)mm * K + k0 + c4 * 4];
            int kt = c4 >> 1, chalf = c4 & 1;
            int mt = r >> 4, rp = r & 15;
            int rlow = rp & 7, rhigh = rp >> 3;
            int reg = chalf * 2 + rhigh;
            uint32_t* p = &sA[((kt * 8 + mt) * 32 + rlow * 4) * 4 + reg];
            p[0]  = f2tf32(v.x);
            p[4]  = f2tf32(v.y);
            p[8]  = f2tf32(v.z);
            p[12] = f2tf32(v.w);
        }
        // --- B tile: 32x128 floats, permuted to mma-fragment order ---
#pragma unroll
        for (int j = 0; j < 4; j++) {
            int i  = tid + j * 256;
            int kr = i >> 5, n4 = i & 31;
            float4 v = *(const float4*)&W[(size_t)(k0 + kr) * NOUT + n0 + n4 * 4];
            int kt = kr >> 3, kp = kr & 7;
            int tig = kp & 3, khigh = kp >> 2;
            int nt = n4 >> 1, nlow = (n4 & 1) * 4;
            uint32_t* p = &sB[((kt * 16 + nt) * 32 + nlow * 4 + tig) * 2 + khigh];
            p[0]  = f2tf32(v.x);
            p[8]  = f2tf32(v.y);
            p[16] = f2tf32(v.z);
            p[24] = f2tf32(v.w);
        }
        __syncthreads();

#pragma unroll
        for (int kt = 0; kt < 4; kt++) {
            uint4 af[2];
            uint2 bfr[8];
#pragma unroll
            for (int mt2 = 0; mt2 < 2; mt2++)
                af[mt2] = *(const uint4*)&sA[((kt * 8 + (wm >> 4) + mt2) * 32 + lane) * 4];
#pragma unroll
            for (int nt2 = 0; nt2 < 8; nt2++)
                bfr[nt2] = *(const uint2*)&sB[((kt * 16 + (wn >> 3) + nt2) * 32 + lane) * 2];
#pragma unroll
            for (int mt2 = 0; mt2 < 2; mt2++)
#pragma unroll
                for (int nt2 = 0; nt2 < 8; nt2++)
                    mma_tf32(acc[mt2][nt2],
                             (const uint32_t*)&af[mt2],
                             (const uint32_t*)&bfr[nt2]);
        }
        __syncthreads();
    }

    // --- epilogue ---
#pragma unroll
    for (int mt2 = 0; mt2 < 2; mt2++) {
        int r0 = m0 + wm + mt2 * 16 + g;
#pragma unroll
        for (int h = 0; h < 2; h++) {
            int r = r0 + h * 8;
            if (r >= M) continue;
#pragma unroll
            for (int nt2 = 0; nt2 < 8; nt2++) {
                int col = n0 + wn + nt2 * 8 + tg * 2;
                float v0 = acc[mt2][nt2][h * 2 + 0] + bias[col];
                float v1 = acc[mt2][nt2][h * 2 + 1] + bias[col + 1];
                if (RELU) { v0 = fmaxf(v0, 0.f); v1 = fmaxf(v1, 0.f); }
                *(float2*)&C[(size_t)r * NOUT + col] = make_float2(v0, v1);
            }
        }
    }
}

// ---------------------------------------------------------------------------
// Per-query predictor: out[q] = relu(A[src] + B[dst]) . Wc2 + bc2
// (bc1 already folded into the a-half bias of AB)
// ---------------------------------------------------------------------------
__global__ void predict_kernel(const float* __restrict__ AB,
                               const int* __restrict__ src,
                               const int* __restrict__ dst,
                               const float* __restrict__ Wc2,
                               const float* __restrict__ bc2,
                               float* __restrict__ out, int Q) {
    int gid  = blockIdx.x * blockDim.x + threadIdx.x;
    int q    = gid >> 5;
    int lane = gid & 31;
    if (q >= Q) return;
    int s = src[q];
    int d = dst[q];
    const float4* ab4 = (const float4*)AB;           // 64 float4 per node row
    float4 a = ab4[(size_t)s * 64 + lane];           // a-part: first 32 float4
    float4 b = ab4[(size_t)d * 64 + 32 + lane];      // b-part: last 32 float4
    float4 w = ((const float4*)Wc2)[lane];
    float v0 = fmaxf(a.x + b.x, 0.0f);
    float v1 = fmaxf(a.y + b.y, 0.0f);
    float v2 = fmaxf(a.z + b.z, 0.0f);
    float v3 = fmaxf(a.w + b.w, 0.0f);
    float acc = v0 * w.x + v1 * w.y + v2 * w.z + v3 * w.w;
#pragma unroll
    for (int o = 16; o > 0; o >>= 1)
        acc += __shfl_down_sync(0xffffffffu, acc, o);
    if (lane == 0) out[q] = acc + bc2[0];
}

// ---------------------------------------------------------------------------
// Launch
// ---------------------------------------------------------------------------
extern "C" void kernel_launch(void* const* d_in, const int* in_sizes, int n_in,
                              void* d_out, int out_size) {
    const float* x   = (const float*)d_in[0];
    const int*   ei  = (const int*)  d_in[1];
    const int*   eli = (const int*)  d_in[2];
    const float* W1  = (const float*)d_in[3];
    const float* b1  = (const float*)d_in[4];
    const float* W2  = (const float*)d_in[5];
    const float* b2  = (const float*)d_in[6];
    const float* Wc1 = (const float*)d_in[7];
    const float* bc1 = (const float*)d_in[8];
    const float* Wc2 = (const float*)d_in[9];
    const float* bc2 = (const float*)d_in[10];
    float* out = (float*)d_out;

    const int N = in_sizes[0] / D_IN;
    const int E = in_sizes[1] / 2;
    const int Q = in_sizes[2] / 2;
    const int* row = ei;
    const int* col = ei + E;
    const int* src = eli;
    const int* dst = eli + Q;

    float *deg, *dis, *agg1, *h1, *agg2, *AB, *Wf, *bf;
    int *cnt, *indptr, *cursor;
    int2 *payload;
    cudaGetSymbolAddress((void**)&deg,     d_deg);
    cudaGetSymbolAddress((void**)&dis,     d_dis);
    cudaGetSymbolAddress((void**)&cnt,     d_cnt);
    cudaGetSymbolAddress((void**)&indptr,  d_indptr);
    cudaGetSymbolAddress((void**)&cursor,  d_cursor);
    cudaGetSymbolAddress((void**)&payload, d_payload);
    cudaGetSymbolAddress((void**)&agg1,    d_agg1);
    cudaGetSymbolAddress((void**)&h1,      d_h1);
    cudaGetSymbolAddress((void**)&agg2,    d_agg2);
    cudaGetSymbolAddress((void**)&AB,      d_AB);
    cudaGetSymbolAddress((void**)&Wf,      d_Wf);
    cudaGetSymbolAddress((void**)&bf,      d_bf);

    const int T = 256;

    // 0. fuse classifier layer1 through conv2 (independent of graph data)
    fuse_weights_kernel<<<dim3(4, 4), 256>>>(W2, Wc1, Wf);
    fuse_bias_kernel   <<<1, 256>>>(b2, Wc1, bc1, bf);

    // 1. degrees (over row) + in-histogram (over col)
    init_counts_kernel<<<(N + T - 1) / T, T>>>(deg, cnt, N);
    count_kernel      <<<(E + T - 1) / T, T>>>(row, col, deg, cnt, E);
    compute_dis_kernel<<<(N + T - 1) / T, T>>>(deg, dis, N);

    // 2. CSR build (by destination col)
    scan_kernel<<<1, 1024>>>(cnt, indptr, cursor, N);
    fill_kernel<<<(E + T - 1) / T, T>>>(row, col, dis, cursor, payload, E);

    // 3. conv1 aggregation: gather, no atomics
    gather1_kernel<<<(N + 7) / 8, 256>>>(x, dis, indptr, payload, agg1, N);

    // 4. h1 = relu(agg1@W1 + b1)
    int gblk = (N + 127) / 128;
    mma_gemm_kernel<D_IN, HID, true><<<dim3(gblk, 1), 256>>>(agg1, W1, b1, h1, N);

    // 5. conv2 aggregation: gather (self loop in-register)
    gather2_kernel<<<(N + 7) / 8, 256>>>(h1, dis, indptr, payload, agg2, N);

    // 6. AB = agg2 @ Wf + bf   (h2 and classifier layer1 in one GEMM)
    mma_gemm_kernel<HID, 2 * HID, false><<<dim3(gblk, 2), 256>>>(agg2, Wf, bf, AB, N);

    // 7. per-query: relu(A[src]+B[dst]) . Wc2 + bc2
    predict_kernel<<<(Q * 32 + T - 1) / T, T>>>(AB, src, dst, Wc2, bc2, out, Q);
}